// round 6
// baseline (speedup 1.0000x reference)
#include <cuda_runtime.h>
#include <cuda_bf16.h>
#include <math.h>

typedef __nv_bfloat16 bf16;

#define BB   2
#define CC   512
#define HWH  4096
#define ICI  256

// ---------------- scratch (__device__ globals; no allocation allowed) ----------------
__device__ float d_mean[2 * BB * CC];
__device__ float d_istd[2 * BB * CC];

__device__ bf16 d_xnT_hi[(size_t)BB * HWH * CC];
__device__ bf16 d_xnT_lo[(size_t)BB * HWH * CC];
__device__ bf16 d_snT_hi[(size_t)BB * HWH * CC];
__device__ bf16 d_snT_lo[(size_t)BB * HWH * CC];
__device__ bf16 d_fsT_hi[(size_t)BB * HWH * CC];
__device__ bf16 d_fsT_lo[(size_t)BB * HWH * CC];

__device__ bf16 d_thw_hi[ICI * CC], d_thw_lo[ICI * CC];
__device__ bf16 d_phw_hi[ICI * CC], d_phw_lo[ICI * CC];
__device__ bf16 d_gw_hi [ICI * CC], d_gw_lo [ICI * CC];
__device__ bf16 d_Ww_hi [CC * ICI], d_Ww_lo [CC * ICI];

__device__ bf16 d_thT_hi[(size_t)BB * HWH * ICI];
__device__ bf16 d_thT_lo[(size_t)BB * HWH * ICI];
__device__ bf16 d_phT_hi[(size_t)BB * HWH * ICI];
__device__ bf16 d_phT_lo[(size_t)BB * HWH * ICI];

__device__ bf16 d_gT_hi[(size_t)BB * ICI * HWH];
__device__ bf16 d_gT_lo[(size_t)BB * ICI * HWH];

__device__ float d_G[(size_t)BB * HWH * HWH];

__device__ bf16 d_P_hi[(size_t)BB * HWH * HWH];
__device__ bf16 d_P_lo[(size_t)BB * HWH * HWH];

__device__ bf16 d_y_hi[(size_t)BB * HWH * ICI];
__device__ bf16 d_y_lo[(size_t)BB * HWH * ICI];

// ------------- stats: per (b,c) mean and 1/std (unbiased var, eps inside sqrt) -------------
__global__ void stats_kernel(const float* __restrict__ content,
                             const float* __restrict__ style) {
    int idx = blockIdx.x;          // 0 .. 2*B*C-1 ; B*C = 1024
    int which = idx >> 10;
    int bc = idx & 1023;
    const float* src = (which == 0 ? content : style) + (size_t)bc * HWH;
    double s = 0.0, s2 = 0.0;
    for (int i = threadIdx.x; i < HWH; i += 256) {
        float v = src[i];
        s += v; s2 += (double)v * v;
    }
    __shared__ double sh1[256], sh2[256];
    sh1[threadIdx.x] = s; sh2[threadIdx.x] = s2;
    __syncthreads();
    for (int st = 128; st > 0; st >>= 1) {
        if (threadIdx.x < st) {
            sh1[threadIdx.x] += sh1[threadIdx.x + st];
            sh2[threadIdx.x] += sh2[threadIdx.x + st];
        }
        __syncthreads();
    }
    if (threadIdx.x == 0) {
        double mean = sh1[0] / (double)HWH;
        double var = (sh2[0] - (double)HWH * mean * mean) / (double)(HWH - 1);
        d_mean[idx] = (float)mean;
        d_istd[idx] = (float)(1.0 / sqrt(var + 1e-5));
    }
}

// ------ normalize (content/style) + transpose to [p][c] + split hi/lo bf16 ------
__global__ void norm_split_T(const float* __restrict__ content,
                             const float* __restrict__ style,
                             const float* __restrict__ fusion) {
    int zz = blockIdx.z;           // src*B + b
    int src = zz >> 1, b = zz & 1;
    const float* in;
    bf16 *oh, *ol;
    if (src == 0)      { in = content; oh = d_xnT_hi; ol = d_xnT_lo; }
    else if (src == 1) { in = style;   oh = d_snT_hi; ol = d_snT_lo; }
    else               { in = fusion;  oh = d_fsT_hi; ol = d_fsT_lo; }
    in += (size_t)b * CC * HWH;
    oh += (size_t)b * HWH * CC;
    ol += (size_t)b * HWH * CC;

    int p0 = blockIdx.x * 32, c0 = blockIdx.y * 32;
    __shared__ float tile[32][33];
    int tx = threadIdx.x, ty = threadIdx.y;  // 32 x 8
    #pragma unroll
    for (int i = 0; i < 4; i++) {
        int c = c0 + ty + i * 8;
        float v = in[(size_t)c * HWH + p0 + tx];
        if (src < 2) {
            int mi = src * 1024 + b * 512 + c;
            v = (v - d_mean[mi]) * d_istd[mi];
        }
        tile[ty + i * 8][tx] = v;  // [c_local][p_local]
    }
    __syncthreads();
    #pragma unroll
    for (int i = 0; i < 4; i++) {
        int p = p0 + ty + i * 8;
        int c = c0 + tx;
        float v = tile[tx][ty + i * 8];
        bf16 h = __float2bfloat16(v);
        size_t off = (size_t)p * CC + c;
        oh[off] = h;
        ol[off] = __float2bfloat16(v - __bfloat162float(h));
    }
}

// ------------- weight split (all four weight mats are 131072 elements) -------------
__global__ void weight_split(const float* __restrict__ tw, const float* __restrict__ pw,
                             const float* __restrict__ gw, const float* __restrict__ Ww) {
    int i = blockIdx.x * 256 + threadIdx.x;
    if (i >= ICI * CC) return;
    float v; bf16 h;
    v = tw[i]; h = __float2bfloat16(v); d_thw_hi[i] = h; d_thw_lo[i] = __float2bfloat16(v - __bfloat162float(h));
    v = pw[i]; h = __float2bfloat16(v); d_phw_hi[i] = h; d_phw_lo[i] = __float2bfloat16(v - __bfloat162float(h));
    v = gw[i]; h = __float2bfloat16(v); d_gw_hi[i]  = h; d_gw_lo[i]  = __float2bfloat16(v - __bfloat162float(h));
    v = Ww[i]; h = __float2bfloat16(v); d_Ww_hi[i]  = h; d_Ww_lo[i]  = __float2bfloat16(v - __bfloat162float(h));
}

// ---------------- generic NT split-bf16 MMA GEMM ----------------
// C[M][N] = sum_k (Ahi+Alo)[m][k]*(Bhi+Blo)[n][k]   (lo*lo dropped; fp32 accum)
#define GBM 128
#define GBN 128
#define GBK 32
#define SPAD 40

__device__ __forceinline__ void mma_bf16(float c[4], const unsigned a[4], const unsigned bb[2]) {
    asm volatile(
        "mma.sync.aligned.m16n8k16.row.col.f32.bf16.bf16.f32 "
        "{%0,%1,%2,%3},{%4,%5,%6,%7},{%8,%9},{%0,%1,%2,%3};\n"
        : "+f"(c[0]), "+f"(c[1]), "+f"(c[2]), "+f"(c[3])
        : "r"(a[0]), "r"(a[1]), "r"(a[2]), "r"(a[3]), "r"(bb[0]), "r"(bb[1]));
}

template<int OUT_MODE /*0 fp32, 1 split bf16*/, int BIAS_MODE /*0 none,1 per-M,2 per-N*/>
__global__ __launch_bounds__(256)
void gemm_nt_split(const bf16* __restrict__ Ahi, const bf16* __restrict__ Alo,
                   const bf16* __restrict__ Bhi, const bf16* __restrict__ Blo,
                   const float* __restrict__ bias,
                   float* __restrict__ Cf, bf16* __restrict__ Chi, bf16* __restrict__ Clo,
                   int M, int N, int K,
                   long long sA, long long sB, long long sC) {
    int bz = blockIdx.z;
    Ahi += (size_t)bz * sA; Alo += (size_t)bz * sA;
    Bhi += (size_t)bz * sB; Blo += (size_t)bz * sB;

    const int m0 = blockIdx.y * GBM;
    const int n0 = blockIdx.x * GBN;

    __shared__ bf16 As[2][GBM][SPAD];
    __shared__ bf16 Bs[2][GBN][SPAD];

    const int tid = threadIdx.x;
    const int warp = tid >> 5, lane = tid & 31;
    const int wm = warp >> 2, wn = warp & 3;
    const int grp = lane >> 2, qid = lane & 3;

    float acc[4][4][4];
    #pragma unroll
    for (int a = 0; a < 4; a++)
        #pragma unroll
        for (int bq = 0; bq < 4; bq++)
            #pragma unroll
            for (int r = 0; r < 4; r++) acc[a][bq][r] = 0.f;

    for (int kt = 0; kt < K; kt += GBK) {
        #pragma unroll
        for (int i = 0; i < 8; i++) {
            int lin = tid + i * 256;
            int row = lin >> 4;
            int cu = lin & 15;
            size_t ga = (size_t)(m0 + row) * K + kt + cu * 2;
            size_t gb = (size_t)(n0 + row) * K + kt + cu * 2;
            *(unsigned*)(&As[0][row][cu * 2]) = *(const unsigned*)(Ahi + ga);
            *(unsigned*)(&As[1][row][cu * 2]) = *(const unsigned*)(Alo + ga);
            *(unsigned*)(&Bs[0][row][cu * 2]) = *(const unsigned*)(Bhi + gb);
            *(unsigned*)(&Bs[1][row][cu * 2]) = *(const unsigned*)(Blo + gb);
        }
        __syncthreads();
        #pragma unroll
        for (int kk = 0; kk < 2; kk++) {
            const int col = kk * 16 + qid * 2;
            unsigned a[4][4], b0[4][2], b1[4][2];
            #pragma unroll
            for (int mm = 0; mm < 4; mm++) {
                int row = wm * 64 + mm * 16 + grp;
                a[mm][0] = *(const unsigned*)(&As[0][row][col]);
                a[mm][1] = *(const unsigned*)(&As[0][row + 8][col]);
                a[mm][2] = *(const unsigned*)(&As[0][row][col + 8]);
                a[mm][3] = *(const unsigned*)(&As[0][row + 8][col + 8]);
            }
            #pragma unroll
            for (int nn = 0; nn < 4; nn++) {
                int nr = wn * 32 + nn * 8 + grp;
                b0[nn][0] = *(const unsigned*)(&Bs[0][nr][col]);
                b0[nn][1] = *(const unsigned*)(&Bs[0][nr][col + 8]);
                b1[nn][0] = *(const unsigned*)(&Bs[1][nr][col]);
                b1[nn][1] = *(const unsigned*)(&Bs[1][nr][col + 8]);
            }
            #pragma unroll
            for (int mm = 0; mm < 4; mm++)
                #pragma unroll
                for (int nn = 0; nn < 4; nn++) {
                    mma_bf16(acc[mm][nn], a[mm], b0[nn]);  // hi*hi
                    mma_bf16(acc[mm][nn], a[mm], b1[nn]);  // hi*lo
                }
            #pragma unroll
            for (int mm = 0; mm < 4; mm++) {
                int row = wm * 64 + mm * 16 + grp;
                a[mm][0] = *(const unsigned*)(&As[1][row][col]);
                a[mm][1] = *(const unsigned*)(&As[1][row + 8][col]);
                a[mm][2] = *(const unsigned*)(&As[1][row][col + 8]);
                a[mm][3] = *(const unsigned*)(&As[1][row + 8][col + 8]);
            }
            #pragma unroll
            for (int mm = 0; mm < 4; mm++)
                #pragma unroll
                for (int nn = 0; nn < 4; nn++)
                    mma_bf16(acc[mm][nn], a[mm], b0[nn]);  // lo*hi
        }
        __syncthreads();
    }

    #pragma unroll
    for (int mm = 0; mm < 4; mm++) {
        #pragma unroll
        for (int nn = 0; nn < 4; nn++) {
            #pragma unroll
            for (int r = 0; r < 4; r++) {
                int row = m0 + wm * 64 + mm * 16 + grp + ((r >> 1) ? 8 : 0);
                int col = n0 + wn * 32 + nn * 8 + qid * 2 + (r & 1);
                float v = acc[mm][nn][r];
                if (BIAS_MODE == 1) v += bias[row];
                if (BIAS_MODE == 2) v += bias[col];
                size_t off = (size_t)bz * sC + (size_t)row * N + col;
                if (OUT_MODE == 0) {
                    Cf[off] = v;
                } else {
                    bf16 h = __float2bfloat16(v);
                    Chi[off] = h;
                    Clo[off] = __float2bfloat16(v - __bfloat162float(h));
                }
            }
        }
    }
}

// ------- fused f-assembly (9-shift gather from G) + softmax + split-P -------
__device__ __forceinline__ int refl(int i) {
    return i < 0 ? -i : (i > 63 ? 126 - i : i);
}

__global__ __launch_bounds__(256)
void attn_softmax_kernel(const float* __restrict__ scale) {
    const int l = blockIdx.x;
    const int b = blockIdx.y;
    const int tid = threadIdx.x;
    const int il = l >> 6, jl = l & 63;

    __shared__ float frow[HWH];
    __shared__ float red[256];

    const float* Gb = d_G + (size_t)b * HWH * HWH;
    const float* gr[9];
    float s2[9];
    #pragma unroll
    for (int k = 0; k < 9; k++) {
        int di = k / 3, dj = k % 3;
        int ri = refl(il + di - 1), rj = refl(jl + dj - 1);
        gr[k] = Gb + (size_t)(ri * 64 + rj) * HWH;
        float s = scale[k];
        s2[k] = s * s;
    }

    for (int m = tid; m < HWH; m += 256) {
        int im = m >> 6, jm = m & 63;
        float acc = 0.f;
        #pragma unroll
        for (int di = 0; di < 3; di++) {
            int ci = refl(im + di - 1) * 64;
            #pragma unroll
            for (int dj = 0; dj < 3; dj++) {
                int cj = refl(jm + dj - 1);
                acc += s2[di * 3 + dj] * gr[di * 3 + dj][ci + cj];
            }
        }
        frow[m] = acc;
    }
    __syncthreads();

    float mx = -3.4e38f;
    for (int m = tid; m < HWH; m += 256) mx = fmaxf(mx, frow[m]);
    red[tid] = mx; __syncthreads();
    for (int st = 128; st > 0; st >>= 1) {
        if (tid < st) red[tid] = fmaxf(red[tid], red[tid + st]);
        __syncthreads();
    }
    mx = red[0];
    __syncthreads();

    float sum = 0.f;
    for (int m = tid; m < HWH; m += 256) {
        float e = expf(frow[m] - mx);
        frow[m] = e;
        sum += e;
    }
    red[tid] = sum; __syncthreads();
    for (int st = 128; st > 0; st >>= 1) {
        if (tid < st) red[tid] += red[tid + st];
        __syncthreads();
    }
    float inv = 1.f / red[0];

    bf16* ph = d_P_hi + ((size_t)b * HWH + l) * HWH;
    bf16* pl = d_P_lo + ((size_t)b * HWH + l) * HWH;
    for (int m = tid; m < HWH; m += 256) {
        float p = frow[m] * inv;
        bf16 h = __float2bfloat16(p);
        ph[m] = h;
        pl[m] = __float2bfloat16(p - __bfloat162float(h));
    }
}

// ---------------- host ----------------
#define SYM(p, s) do { void* _t; cudaGetSymbolAddress(&_t, s); p = (decltype(p))_t; } while (0)

extern "C" void kernel_launch(void* const* d_in, const int* in_sizes, int n_in,
                              void* d_out, int out_size) {
    const float* content = (const float*)d_in[0];
    const float* style   = (const float*)d_in[1];
    const float* fusion  = (const float*)d_in[2];
    const float* theta_b = (const float*)d_in[4];
    const float* phi_b   = (const float*)d_in[6];
    const float* g_b     = (const float*)d_in[8];
    const float* W_b     = (const float*)d_in[10];
    const float* scale   = (const float*)d_in[11];
    float* out = (float*)d_out;

    bf16 *xnT_hi, *xnT_lo, *snT_hi, *snT_lo, *fsT_hi, *fsT_lo;
    bf16 *thw_hi, *thw_lo, *phw_hi, *phw_lo, *gw_hi, *gw_lo, *Ww_hi, *Ww_lo;
    bf16 *thT_hi, *thT_lo, *phT_hi, *phT_lo, *gT_hi, *gT_lo;
    bf16 *P_hi, *P_lo, *y_hi, *y_lo;
    float* Gp;
    SYM(xnT_hi, d_xnT_hi); SYM(xnT_lo, d_xnT_lo);
    SYM(snT_hi, d_snT_hi); SYM(snT_lo, d_snT_lo);
    SYM(fsT_hi, d_fsT_hi); SYM(fsT_lo, d_fsT_lo);
    SYM(thw_hi, d_thw_hi); SYM(thw_lo, d_thw_lo);
    SYM(phw_hi, d_phw_hi); SYM(phw_lo, d_phw_lo);
    SYM(gw_hi,  d_gw_hi);  SYM(gw_lo,  d_gw_lo);
    SYM(Ww_hi,  d_Ww_hi);  SYM(Ww_lo,  d_Ww_lo);
    SYM(thT_hi, d_thT_hi); SYM(thT_lo, d_thT_lo);
    SYM(phT_hi, d_phT_hi); SYM(phT_lo, d_phT_lo);
    SYM(gT_hi,  d_gT_hi);  SYM(gT_lo,  d_gT_lo);
    SYM(P_hi,   d_P_hi);   SYM(P_lo,   d_P_lo);
    SYM(y_hi,   d_y_hi);   SYM(y_lo,   d_y_lo);
    SYM(Gp,     d_G);

    // 1) instance-norm stats
    stats_kernel<<<2 * BB * CC, 256>>>(content, style);
    // 2) normalize + transpose + split (content, style, fusion)
    norm_split_T<<<dim3(HWH / 32, CC / 32, 3 * BB), dim3(32, 8)>>>(content, style, fusion);
    // 3) weight splits
    weight_split<<<(ICI * CC) / 256, 256>>>((const float*)d_in[3], (const float*)d_in[5],
                                            (const float*)d_in[7], (const float*)d_in[9]);

    // 4) theta_xT = xnT @ theta_w^T + theta_b : M=4096, N=256, K=512, bias per-N
    gemm_nt_split<1, 2><<<dim3(ICI / GBN, HWH / GBM, BB), 256>>>(
        xnT_hi, xnT_lo, thw_hi, thw_lo, theta_b,
        nullptr, thT_hi, thT_lo,
        HWH, ICI, CC, (long long)HWH * CC, 0, (long long)HWH * ICI);

    // 5) phi_sT = snT @ phi_w^T + phi_b
    gemm_nt_split<1, 2><<<dim3(ICI / GBN, HWH / GBM, BB), 256>>>(
        snT_hi, snT_lo, phw_hi, phw_lo, phi_b,
        nullptr, phT_hi, phT_lo,
        HWH, ICI, CC, (long long)HWH * CC, 0, (long long)HWH * ICI);

    // 6) g_sT = g_w @ fsT^T + g_b : M=256, N=4096, K=512, bias per-M -> gT [IC][HW]
    gemm_nt_split<1, 1><<<dim3(HWH / GBN, ICI / GBM, BB), 256>>>(
        gw_hi, gw_lo, fsT_hi, fsT_lo, g_b,
        nullptr, gT_hi, gT_lo,
        ICI, HWH, CC, 0, (long long)HWH * CC, (long long)ICI * HWH);

    // 7) G = theta_xT @ phi_sT^T : M=N=4096, K=256, fp32 out
    gemm_nt_split<0, 0><<<dim3(HWH / GBN, HWH / GBM, BB), 256>>>(
        thT_hi, thT_lo, phT_hi, phT_lo, nullptr,
        Gp, nullptr, nullptr,
        HWH, HWH, ICI, (long long)HWH * ICI, (long long)HWH * ICI, (long long)HWH * HWH);

    // 8) f assembly (9 reflected shifts of G, scale^2) + softmax -> P (split)
    attn_softmax_kernel<<<dim3(HWH, BB), 256>>>(scale);

    // 9) y = P @ g_s : M=4096, N=256, K=4096 -> y [HW][IC] split
    gemm_nt_split<1, 0><<<dim3(ICI / GBN, HWH / GBM, BB), 256>>>(
        P_hi, P_lo, gT_hi, gT_lo, nullptr,
        nullptr, y_hi, y_lo,
        HWH, ICI, HWH, (long long)HWH * HWH, (long long)ICI * HWH, (long long)HWH * ICI);

    // 10) out = W_w @ y^T + W_b : M=512, N=4096, K=256, bias per-M, fp32 out
    gemm_nt_split<0, 1><<<dim3(HWH / GBN, CC / GBM, BB), 256>>>(
        Ww_hi, Ww_lo, y_hi, y_lo, W_b,
        out, nullptr, nullptr,
        CC, HWH, ICI, 0, (long long)HWH * ICI, (long long)CC * HWH);
}

// round 7
// speedup vs baseline: 1.2481x; 1.2481x over previous
#include <cuda_runtime.h>
#include <cuda_bf16.h>
#include <cuda_fp16.h>
#include <math.h>

typedef __nv_bfloat16 bf16;
typedef __half f16;

#define BB   2
#define CC   512
#define HWH  4096
#define ICI  256
#define SPAD 40

// ---------------- scratch ----------------
__device__ float d_mean[2 * BB * CC];
__device__ float d_istd[2 * BB * CC];

__device__ bf16 d_xnT_hi[(size_t)BB * HWH * CC];
__device__ bf16 d_xnT_lo[(size_t)BB * HWH * CC];
__device__ bf16 d_snT_hi[(size_t)BB * HWH * CC];
__device__ bf16 d_snT_lo[(size_t)BB * HWH * CC];
__device__ bf16 d_fsT_hi[(size_t)BB * HWH * CC];
__device__ bf16 d_fsT_lo[(size_t)BB * HWH * CC];

__device__ bf16 d_thw_hi[ICI * CC], d_thw_lo[ICI * CC];
__device__ bf16 d_phw_hi[ICI * CC], d_phw_lo[ICI * CC];
__device__ bf16 d_gw_hi [ICI * CC], d_gw_lo [ICI * CC];
__device__ bf16 d_Ww_hi [CC * ICI], d_Ww_lo [CC * ICI];

__device__ bf16 d_thT_hi[(size_t)BB * HWH * ICI];
__device__ bf16 d_thT_lo[(size_t)BB * HWH * ICI];
__device__ bf16 d_phT_hi[(size_t)BB * HWH * ICI];
__device__ bf16 d_phT_lo[(size_t)BB * HWH * ICI];

__device__ f16 d_gT_hi[(size_t)BB * ICI * HWH];
__device__ f16 d_gT_lo[(size_t)BB * ICI * HWH];

__device__ float d_G[(size_t)BB * HWH * HWH];

__device__ f16 d_P[(size_t)BB * HWH * HWH];

__device__ bf16 d_y_hi[(size_t)BB * HWH * ICI];
__device__ bf16 d_y_lo[(size_t)BB * HWH * ICI];

// ------------- stats -------------
__global__ void stats_kernel(const float* __restrict__ content,
                             const float* __restrict__ style) {
    int idx = blockIdx.x;
    int which = idx >> 10;
    int bc = idx & 1023;
    const float* src = (which == 0 ? content : style) + (size_t)bc * HWH;
    double s = 0.0, s2 = 0.0;
    for (int i = threadIdx.x; i < HWH; i += 256) {
        float v = src[i];
        s += v; s2 += (double)v * v;
    }
    __shared__ double sh1[256], sh2[256];
    sh1[threadIdx.x] = s; sh2[threadIdx.x] = s2;
    __syncthreads();
    for (int st = 128; st > 0; st >>= 1) {
        if (threadIdx.x < st) {
            sh1[threadIdx.x] += sh1[threadIdx.x + st];
            sh2[threadIdx.x] += sh2[threadIdx.x + st];
        }
        __syncthreads();
    }
    if (threadIdx.x == 0) {
        double mean = sh1[0] / (double)HWH;
        double var = (sh2[0] - (double)HWH * mean * mean) / (double)(HWH - 1);
        d_mean[idx] = (float)mean;
        d_istd[idx] = (float)(1.0 / sqrt(var + 1e-5));
    }
}

// ------ normalize + transpose + split ------
__global__ void norm_split_T(const float* __restrict__ content,
                             const float* __restrict__ style,
                             const float* __restrict__ fusion) {
    int zz = blockIdx.z;
    int src = zz >> 1, b = zz & 1;
    const float* in;
    bf16 *oh, *ol;
    if (src == 0)      { in = content; oh = d_xnT_hi; ol = d_xnT_lo; }
    else if (src == 1) { in = style;   oh = d_snT_hi; ol = d_snT_lo; }
    else               { in = fusion;  oh = d_fsT_hi; ol = d_fsT_lo; }
    in += (size_t)b * CC * HWH;
    oh += (size_t)b * HWH * CC;
    ol += (size_t)b * HWH * CC;

    int p0 = blockIdx.x * 32, c0 = blockIdx.y * 32;
    __shared__ float tile[32][33];
    int tx = threadIdx.x, ty = threadIdx.y;
    #pragma unroll
    for (int i = 0; i < 4; i++) {
        int c = c0 + ty + i * 8;
        float v = in[(size_t)c * HWH + p0 + tx];
        if (src < 2) {
            int mi = src * 1024 + b * 512 + c;
            v = (v - d_mean[mi]) * d_istd[mi];
        }
        tile[ty + i * 8][tx] = v;
    }
    __syncthreads();
    #pragma unroll
    for (int i = 0; i < 4; i++) {
        int p = p0 + ty + i * 8;
        int c = c0 + tx;
        float v = tile[tx][ty + i * 8];
        bf16 h = __float2bfloat16(v);
        size_t off = (size_t)p * CC + c;
        oh[off] = h;
        ol[off] = __float2bfloat16(v - __bfloat162float(h));
    }
}

// ------------- weight split -------------
__global__ void weight_split(const float* __restrict__ tw, const float* __restrict__ pw,
                             const float* __restrict__ gw, const float* __restrict__ Ww) {
    int i = blockIdx.x * 256 + threadIdx.x;
    if (i >= ICI * CC) return;
    float v; bf16 h;
    v = tw[i]; h = __float2bfloat16(v); d_thw_hi[i] = h; d_thw_lo[i] = __float2bfloat16(v - __bfloat162float(h));
    v = pw[i]; h = __float2bfloat16(v); d_phw_hi[i] = h; d_phw_lo[i] = __float2bfloat16(v - __bfloat162float(h));
    v = gw[i]; h = __float2bfloat16(v); d_gw_hi[i]  = h; d_gw_lo[i]  = __float2bfloat16(v - __bfloat162float(h));
    v = Ww[i]; h = __float2bfloat16(v); d_Ww_hi[i]  = h; d_Ww_lo[i]  = __float2bfloat16(v - __bfloat162float(h));
}

// ---------------- cp.async helpers ----------------
__device__ __forceinline__ void cp16(void* dst, const void* src) {
    unsigned d = (unsigned)__cvta_generic_to_shared(dst);
    asm volatile("cp.async.cg.shared.global [%0], [%1], 16;\n" :: "r"(d), "l"(src));
}
__device__ __forceinline__ void cp_commit() { asm volatile("cp.async.commit_group;\n"); }
template<int N> __device__ __forceinline__ void cp_wait() {
    asm volatile("cp.async.wait_group %0;\n" :: "n"(N));
}

template<int DT>
__device__ __forceinline__ void mma2(float c[4], const unsigned a[4], const unsigned b[2]) {
    if (DT == 0)
        asm volatile(
            "mma.sync.aligned.m16n8k16.row.col.f32.bf16.bf16.f32 "
            "{%0,%1,%2,%3},{%4,%5,%6,%7},{%8,%9},{%0,%1,%2,%3};\n"
            : "+f"(c[0]), "+f"(c[1]), "+f"(c[2]), "+f"(c[3])
            : "r"(a[0]), "r"(a[1]), "r"(a[2]), "r"(a[3]), "r"(b[0]), "r"(b[1]));
    else
        asm volatile(
            "mma.sync.aligned.m16n8k16.row.col.f32.f16.f16.f32 "
            "{%0,%1,%2,%3},{%4,%5,%6,%7},{%8,%9},{%0,%1,%2,%3};\n"
            : "+f"(c[0]), "+f"(c[1]), "+f"(c[2]), "+f"(c[3])
            : "r"(a[0]), "r"(a[1]), "r"(a[2]), "r"(a[3]), "r"(b[0]), "r"(b[1]));
}

// ---------------- pipelined generic NT GEMM ----------------
// C[M][N] = sum_k A[m,k]*B[n,k]; A = Ahi(+Alo if ASPL), B = Bhi(+Blo if BSPL).
// Passes: hi*hi (+ hi*lo if BSPL) (+ lo*hi if ASPL). fp32 accum.
// DT: 0 bf16, 1 fp16. OUTM: 0 fp32, 1 split bf16, 2 split fp16.
// BIASM: 0 none, 1 per-row(M), 2 per-col(N).
template<int DT, int ASPL, int BSPL, int OUTM, int BIASM, int WM_, int WN_, int BM, int BN>
__global__ __launch_bounds__(256)
void gemm_pl(const void* __restrict__ Ahi_, const void* __restrict__ Alo_,
             const void* __restrict__ Bhi_, const void* __restrict__ Blo_,
             const float* __restrict__ bias,
             void* __restrict__ C0, void* __restrict__ C1,
             int M, int N, int K,
             long long sA, long long sB, long long sC) {
    constexpr int NPA = 1 + ASPL, NPB = 1 + BSPL;
    constexpr int FM = BM / (16 * WM_), FN = BN / (8 * WN_);
    constexpr int SSTR = (NPA * BM + NPB * BN) * SPAD;
    extern __shared__ unsigned short sh[];

    const int bz = blockIdx.z;
    const unsigned short* Ah = (const unsigned short*)Ahi_ + (size_t)bz * sA;
    const unsigned short* Al = (const unsigned short*)Alo_ + (size_t)bz * sA;
    const unsigned short* Bh = (const unsigned short*)Bhi_ + (size_t)bz * sB;
    const unsigned short* Bl = (const unsigned short*)Blo_ + (size_t)bz * sB;

    const int m0 = blockIdx.y * BM, n0 = blockIdx.x * BN;
    const int tid = threadIdx.x, warp = tid >> 5, lane = tid & 31;
    const int wm = warp / WN_, wn = warp % WN_;
    const int grp = lane >> 2, qid = lane & 3;

    float acc[FM][FN][4] = {};

    auto load_stage = [&](int st, int kt) {
        unsigned short* s = sh + st * SSTR;
        #pragma unroll
        for (int p = 0; p < NPA; p++) {
            const unsigned short* g = p ? Al : Ah;
            #pragma unroll
            for (int cid = tid; cid < BM * 4; cid += 256) {
                int row = cid >> 2, seg = cid & 3;
                cp16(s + p * BM * SPAD + row * SPAD + seg * 8,
                     g + (size_t)(m0 + row) * K + kt + seg * 8);
            }
        }
        unsigned short* sb = s + NPA * BM * SPAD;
        #pragma unroll
        for (int p = 0; p < NPB; p++) {
            const unsigned short* g = p ? Bl : Bh;
            #pragma unroll
            for (int cid = tid; cid < BN * 4; cid += 256) {
                int row = cid >> 2, seg = cid & 3;
                cp16(sb + p * BN * SPAD + row * SPAD + seg * 8,
                     g + (size_t)(n0 + row) * K + kt + seg * 8);
            }
        }
    };

    load_stage(0, 0);
    cp_commit();

    const int KT = K / 32;
    for (int it = 0; it < KT; ++it) {
        const int st = it & 1;
        if (it + 1 < KT) {
            load_stage(st ^ 1, (it + 1) * 32);
            cp_commit();
            cp_wait<1>();
        } else {
            cp_wait<0>();
        }
        __syncthreads();

        const unsigned short* sA0 = sh + st * SSTR;
        const unsigned short* sA1 = sA0 + BM * SPAD;
        const unsigned short* sB0 = sh + st * SSTR + NPA * BM * SPAD;
        const unsigned short* sB1 = sB0 + BN * SPAD;

        #pragma unroll
        for (int kk = 0; kk < 2; kk++) {
            const int col = kk * 16 + qid * 2;
            unsigned a[FM][4], b0[FN][2], b1[FN][2];
            #pragma unroll
            for (int mm = 0; mm < FM; mm++) {
                int row = wm * (FM * 16) + mm * 16 + grp;
                a[mm][0] = *(const unsigned*)(sA0 + row * SPAD + col);
                a[mm][1] = *(const unsigned*)(sA0 + (row + 8) * SPAD + col);
                a[mm][2] = *(const unsigned*)(sA0 + row * SPAD + col + 8);
                a[mm][3] = *(const unsigned*)(sA0 + (row + 8) * SPAD + col + 8);
            }
            #pragma unroll
            for (int nn = 0; nn < FN; nn++) {
                int nr = wn * (FN * 8) + nn * 8 + grp;
                b0[nn][0] = *(const unsigned*)(sB0 + nr * SPAD + col);
                b0[nn][1] = *(const unsigned*)(sB0 + nr * SPAD + col + 8);
                if (BSPL) {
                    b1[nn][0] = *(const unsigned*)(sB1 + nr * SPAD + col);
                    b1[nn][1] = *(const unsigned*)(sB1 + nr * SPAD + col + 8);
                }
            }
            #pragma unroll
            for (int mm = 0; mm < FM; mm++)
                #pragma unroll
                for (int nn = 0; nn < FN; nn++) {
                    mma2<DT>(acc[mm][nn], a[mm], b0[nn]);
                    if (BSPL) mma2<DT>(acc[mm][nn], a[mm], b1[nn]);
                }
            if (ASPL) {
                #pragma unroll
                for (int mm = 0; mm < FM; mm++) {
                    int row = wm * (FM * 16) + mm * 16 + grp;
                    a[mm][0] = *(const unsigned*)(sA1 + row * SPAD + col);
                    a[mm][1] = *(const unsigned*)(sA1 + (row + 8) * SPAD + col);
                    a[mm][2] = *(const unsigned*)(sA1 + row * SPAD + col + 8);
                    a[mm][3] = *(const unsigned*)(sA1 + (row + 8) * SPAD + col + 8);
                }
                #pragma unroll
                for (int mm = 0; mm < FM; mm++)
                    #pragma unroll
                    for (int nn = 0; nn < FN; nn++)
                        mma2<DT>(acc[mm][nn], a[mm], b0[nn]);
            }
        }
        __syncthreads();
    }

    #pragma unroll
    for (int mm = 0; mm < FM; mm++) {
        #pragma unroll
        for (int nn = 0; nn < FN; nn++) {
            #pragma unroll
            for (int r = 0; r < 4; r++) {
                int row = m0 + wm * (FM * 16) + mm * 16 + grp + ((r >> 1) ? 8 : 0);
                int col = n0 + wn * (FN * 8) + nn * 8 + qid * 2 + (r & 1);
                float v = acc[mm][nn][r];
                if (BIASM == 1) v += bias[row];
                if (BIASM == 2) v += bias[col];
                size_t off = (size_t)bz * sC + (size_t)row * N + col;
                if (OUTM == 0) {
                    ((float*)C0)[off] = v;
                } else if (OUTM == 1) {
                    bf16 h = __float2bfloat16(v);
                    ((bf16*)C0)[off] = h;
                    ((bf16*)C1)[off] = __float2bfloat16(v - __bfloat162float(h));
                } else {
                    f16 h = __float2half_rn(v);
                    ((f16*)C0)[off] = h;
                    ((f16*)C1)[off] = __float2half_rn(v - __half2float(h));
                }
            }
        }
    }
}

// ------- fused f-assembly + softmax, register-resident, P -> fp16 -------
__device__ __forceinline__ int refl(int i) {
    return i < 0 ? -i : (i > 63 ? 126 - i : i);
}

__global__ __launch_bounds__(256)
void attn_softmax_kernel(const float* __restrict__ scale) {
    const int l = blockIdx.x;
    const int b = blockIdx.y;
    const int tid = threadIdx.x;
    const int il = l >> 6, jl = l & 63;

    __shared__ float red[256];

    const float* Gb = d_G + (size_t)b * HWH * HWH;
    const float* gr[9];
    float s2[9];
    #pragma unroll
    for (int k = 0; k < 9; k++) {
        int di = k / 3, dj = k % 3;
        gr[k] = Gb + (size_t)(refl(il + di - 1) * 64 + refl(jl + dj - 1)) * HWH;
        float s = scale[k];
        s2[k] = s * s;
    }

    float v[16];
    float mx = -3.4e38f;
    #pragma unroll
    for (int i = 0; i < 16; i++) {
        int m = tid + i * 256;
        int im = m >> 6, jm = m & 63;
        float acc = 0.f;
        #pragma unroll
        for (int di = 0; di < 3; di++) {
            int ci = refl(im + di - 1) * 64;
            #pragma unroll
            for (int dj = 0; dj < 3; dj++)
                acc += s2[di * 3 + dj] * gr[di * 3 + dj][ci + refl(jm + dj - 1)];
        }
        v[i] = acc;
        mx = fmaxf(mx, acc);
    }
    red[tid] = mx; __syncthreads();
    for (int st = 128; st > 0; st >>= 1) {
        if (tid < st) red[tid] = fmaxf(red[tid], red[tid + st]);
        __syncthreads();
    }
    mx = red[0];
    __syncthreads();

    float sum = 0.f;
    #pragma unroll
    for (int i = 0; i < 16; i++) {
        v[i] = __expf(v[i] - mx);
        sum += v[i];
    }
    red[tid] = sum; __syncthreads();
    for (int st = 128; st > 0; st >>= 1) {
        if (tid < st) red[tid] += red[tid + st];
        __syncthreads();
    }
    float inv = 1.f / red[0];

    f16* pr = d_P + ((size_t)b * HWH + l) * HWH;
    #pragma unroll
    for (int i = 0; i < 16; i++)
        pr[tid + i * 256] = __float2half_rn(v[i] * inv);
}

// ---------------- host ----------------
#define SYM(p, s) do { void* _t; cudaGetSymbolAddress(&_t, s); p = (decltype(p))_t; } while (0)

#define LAUNCH_GEMM(DT, ASPL, BSPL, OUTM, BIASM, WM, WN, BM, BN, Ah, Al, Bh, Bl, bias, C0, C1, M, N, K, sa, sb, sc) \
    do { \
        auto kfn = gemm_pl<DT, ASPL, BSPL, OUTM, BIASM, WM, WN, BM, BN>; \
        int smemB = 2 * ((1 + ASPL) * (BM) + (1 + BSPL) * (BN)) * SPAD * 2; \
        cudaFuncSetAttribute(kfn, cudaFuncAttributeMaxDynamicSharedMemorySize, smemB); \
        kfn<<<dim3((N) / (BN), (M) / (BM), BB), 256, smemB>>>( \
            Ah, Al, Bh, Bl, bias, C0, C1, M, N, K, sa, sb, sc); \
    } while (0)

extern "C" void kernel_launch(void* const* d_in, const int* in_sizes, int n_in,
                              void* d_out, int out_size) {
    const float* content = (const float*)d_in[0];
    const float* style   = (const float*)d_in[1];
    const float* fusion  = (const float*)d_in[2];
    const float* theta_b = (const float*)d_in[4];
    const float* phi_b   = (const float*)d_in[6];
    const float* g_b     = (const float*)d_in[8];
    const float* W_b     = (const float*)d_in[10];
    const float* scale   = (const float*)d_in[11];
    float* out = (float*)d_out;

    bf16 *xnT_hi, *xnT_lo, *snT_hi, *snT_lo, *fsT_hi, *fsT_lo;
    bf16 *thw_hi, *thw_lo, *phw_hi, *phw_lo, *gw_hi, *gw_lo, *Ww_hi, *Ww_lo;
    bf16 *thT_hi, *thT_lo, *phT_hi, *phT_lo;
    f16 *gT_hi, *gT_lo, *Pp;
    bf16 *y_hi, *y_lo;
    float* Gp;
    SYM(xnT_hi, d_xnT_hi); SYM(xnT_lo, d_xnT_lo);
    SYM(snT_hi, d_snT_hi); SYM(snT_lo, d_snT_lo);
    SYM(fsT_hi, d_fsT_hi); SYM(fsT_lo, d_fsT_lo);
    SYM(thw_hi, d_thw_hi); SYM(thw_lo, d_thw_lo);
    SYM(phw_hi, d_phw_hi); SYM(phw_lo, d_phw_lo);
    SYM(gw_hi,  d_gw_hi);  SYM(gw_lo,  d_gw_lo);
    SYM(Ww_hi,  d_Ww_hi);  SYM(Ww_lo,  d_Ww_lo);
    SYM(thT_hi, d_thT_hi); SYM(thT_lo, d_thT_lo);
    SYM(phT_hi, d_phT_hi); SYM(phT_lo, d_phT_lo);
    SYM(gT_hi,  d_gT_hi);  SYM(gT_lo,  d_gT_lo);
    SYM(Pp,     d_P);
    SYM(y_hi,   d_y_hi);   SYM(y_lo,   d_y_lo);
    SYM(Gp,     d_G);

    // 1) instance-norm stats
    stats_kernel<<<2 * BB * CC, 256>>>(content, style);
    // 2) normalize + transpose + split
    norm_split_T<<<dim3(HWH / 32, CC / 32, 3 * BB), dim3(32, 8)>>>(content, style, fusion);
    // 3) weight splits
    weight_split<<<(ICI * CC) / 256, 256>>>((const float*)d_in[3], (const float*)d_in[5],
                                            (const float*)d_in[7], (const float*)d_in[9]);

    // 4) theta_xT = xnT @ theta_w^T + theta_b : M=4096, N=256, K=512 (skinny, split bf16 out)
    LAUNCH_GEMM(0, 1, 1, 1, 2, 4, 2, 128, 64,
                xnT_hi, xnT_lo, thw_hi, thw_lo, theta_b, thT_hi, thT_lo,
                HWH, ICI, CC, (long long)HWH * CC, 0LL, (long long)HWH * ICI);

    // 5) phi_sT = snT @ phi_w^T + phi_b
    LAUNCH_GEMM(0, 1, 1, 1, 2, 4, 2, 128, 64,
                snT_hi, snT_lo, phw_hi, phw_lo, phi_b, phT_hi, phT_lo,
                HWH, ICI, CC, (long long)HWH * CC, 0LL, (long long)HWH * ICI);

    // 6) g_sT = g_w @ fsT^T + g_b : M=256, N=4096, K=512 (skinny, split fp16 out)
    LAUNCH_GEMM(0, 1, 1, 2, 1, 4, 2, 128, 64,
                gw_hi, gw_lo, fsT_hi, fsT_lo, g_b, gT_hi, gT_lo,
                ICI, HWH, CC, 0LL, (long long)HWH * CC, (long long)ICI * HWH);

    // 7) G = theta_xT @ phi_sT^T : M=N=4096, K=256, fp32 out (big tiles)
    LAUNCH_GEMM(0, 1, 1, 0, 0, 2, 4, 128, 128,
                thT_hi, thT_lo, phT_hi, phT_lo, (const float*)nullptr, Gp, (void*)nullptr,
                HWH, HWH, ICI, (long long)HWH * ICI, (long long)HWH * ICI, (long long)HWH * HWH);

    // 8) gather + softmax -> P (single fp16)
    attn_softmax_kernel<<<dim3(HWH, BB), 256>>>(scale);

    // 9) y = P @ g_s : M=4096, N=256, K=4096, fp16 A single / fp16 B split, 2 passes
    LAUNCH_GEMM(1, 0, 1, 1, 0, 4, 2, 128, 64,
                Pp, Pp, gT_hi, gT_lo, (const float*)nullptr, y_hi, y_lo,
                HWH, ICI, HWH, (long long)HWH * HWH, (long long)ICI * HWH, (long long)HWH * ICI);

    // 10) out = W_w @ y^T + W_b : M=512, N=4096, K=256, fp32 out (big tiles)
    LAUNCH_GEMM(0, 1, 1, 0, 1, 2, 4, 128, 128,
                Ww_hi, Ww_lo, y_hi, y_lo, W_b, out, (void*)nullptr,
                CC, HWH, ICI, 0LL, (long long)HWH * ICI, (long long)CC * HWH);
}

// round 9
// speedup vs baseline: 1.4667x; 1.1751x over previous
#include <cuda_runtime.h>
#include <cuda_bf16.h>
#include <cuda_fp16.h>
#include <math.h>
#include <stdint.h>

typedef __nv_bfloat16 bf16;
typedef __half f16;

#define BB   2
#define CC   512
#define HWH  4096
#define ICI  256
#define SPAD 40

// ---------------- scratch ----------------
__device__ float d_mean[2 * BB * CC];
__device__ float d_istd[2 * BB * CC];

__device__ bf16 d_xnT_hi[(size_t)BB * HWH * CC];
__device__ bf16 d_xnT_lo[(size_t)BB * HWH * CC];
__device__ bf16 d_snT_hi[(size_t)BB * HWH * CC];
__device__ bf16 d_snT_lo[(size_t)BB * HWH * CC];
__device__ bf16 d_fsT_hi[(size_t)BB * HWH * CC];
__device__ bf16 d_fsT_lo[(size_t)BB * HWH * CC];

__device__ bf16 d_thw_hi[ICI * CC], d_thw_lo[ICI * CC];
__device__ bf16 d_phw_hi[ICI * CC], d_phw_lo[ICI * CC];
__device__ bf16 d_gw_hi [ICI * CC], d_gw_lo [ICI * CC];
__device__ bf16 d_Ww_hi [CC * ICI], d_Ww_lo [CC * ICI];

__device__ bf16 d_thT_hi[(size_t)BB * HWH * ICI];
__device__ bf16 d_thT_lo[(size_t)BB * HWH * ICI];
__device__ bf16 d_phT_hi[(size_t)BB * HWH * ICI];
__device__ bf16 d_phT_lo[(size_t)BB * HWH * ICI];

__device__ f16 d_gT_hi[(size_t)BB * ICI * HWH];
__device__ f16 d_gT_lo[(size_t)BB * ICI * HWH];

__device__ float d_G[(size_t)BB * HWH * HWH];

__device__ f16 d_P[(size_t)BB * HWH * HWH];

__device__ bf16 d_y_hi[(size_t)BB * HWH * ICI];
__device__ bf16 d_y_lo[(size_t)BB * HWH * ICI];

// ------------- stats -------------
__global__ void stats_kernel(const float* __restrict__ content,
                             const float* __restrict__ style) {
    int idx = blockIdx.x;
    int which = idx >> 10;
    int bc = idx & 1023;
    const float* src = (which == 0 ? content : style) + (size_t)bc * HWH;
    double s = 0.0, s2 = 0.0;
    for (int i = threadIdx.x; i < HWH; i += 256) {
        float v = src[i];
        s += v; s2 += (double)v * v;
    }
    __shared__ double sh1[256], sh2[256];
    sh1[threadIdx.x] = s; sh2[threadIdx.x] = s2;
    __syncthreads();
    for (int st = 128; st > 0; st >>= 1) {
        if (threadIdx.x < st) {
            sh1[threadIdx.x] += sh1[threadIdx.x + st];
            sh2[threadIdx.x] += sh2[threadIdx.x + st];
        }
        __syncthreads();
    }
    if (threadIdx.x == 0) {
        double mean = sh1[0] / (double)HWH;
        double var = (sh2[0] - (double)HWH * mean * mean) / (double)(HWH - 1);
        d_mean[idx] = (float)mean;
        d_istd[idx] = (float)(1.0 / sqrt(var + 1e-5));
    }
}

// ------ normalize + transpose + split ------
__global__ void norm_split_T(const float* __restrict__ content,
                             const float* __restrict__ style,
                             const float* __restrict__ fusion) {
    int zz = blockIdx.z;
    int src = zz >> 1, b = zz & 1;
    const float* in;
    bf16 *oh, *ol;
    if (src == 0)      { in = content; oh = d_xnT_hi; ol = d_xnT_lo; }
    else if (src == 1) { in = style;   oh = d_snT_hi; ol = d_snT_lo; }
    else               { in = fusion;  oh = d_fsT_hi; ol = d_fsT_lo; }
    in += (size_t)b * CC * HWH;
    oh += (size_t)b * HWH * CC;
    ol += (size_t)b * HWH * CC;

    int p0 = blockIdx.x * 32, c0 = blockIdx.y * 32;
    __shared__ float tile[32][33];
    int tx = threadIdx.x, ty = threadIdx.y;
    #pragma unroll
    for (int i = 0; i < 4; i++) {
        int c = c0 + ty + i * 8;
        float v = in[(size_t)c * HWH + p0 + tx];
        if (src < 2) {
            int mi = src * 1024 + b * 512 + c;
            v = (v - d_mean[mi]) * d_istd[mi];
        }
        tile[ty + i * 8][tx] = v;
    }
    __syncthreads();
    #pragma unroll
    for (int i = 0; i < 4; i++) {
        int p = p0 + ty + i * 8;
        int c = c0 + tx;
        float v = tile[tx][ty + i * 8];
        bf16 h = __float2bfloat16(v);
        size_t off = (size_t)p * CC + c;
        oh[off] = h;
        ol[off] = __float2bfloat16(v - __bfloat162float(h));
    }
}

// ------------- weight split -------------
__global__ void weight_split(const float* __restrict__ tw, const float* __restrict__ pw,
                             const float* __restrict__ gw, const float* __restrict__ Ww) {
    int i = blockIdx.x * 256 + threadIdx.x;
    if (i >= ICI * CC) return;
    float v; bf16 h;
    v = tw[i]; h = __float2bfloat16(v); d_thw_hi[i] = h; d_thw_lo[i] = __float2bfloat16(v - __bfloat162float(h));
    v = pw[i]; h = __float2bfloat16(v); d_phw_hi[i] = h; d_phw_lo[i] = __float2bfloat16(v - __bfloat162float(h));
    v = gw[i]; h = __float2bfloat16(v); d_gw_hi[i]  = h; d_gw_lo[i]  = __float2bfloat16(v - __bfloat162float(h));
    v = Ww[i]; h = __float2bfloat16(v); d_Ww_hi[i]  = h; d_Ww_lo[i]  = __float2bfloat16(v - __bfloat162float(h));
}

// ---------------- low-level helpers ----------------
__device__ __forceinline__ uint32_t smem_u32(const void* p) {
    uint32_t a;
    asm("{ .reg .u64 t; cvta.to.shared.u64 t, %1; cvt.u32.u64 %0, t; }"
        : "=r"(a) : "l"(p));
    return a;
}

__device__ __forceinline__ void cp16(uint32_t dst, const void* src) {
    asm volatile("cp.async.cg.shared.global [%0], [%1], 16;\n" :: "r"(dst), "l"(src));
}
__device__ __forceinline__ void cp_commit() { asm volatile("cp.async.commit_group;\n"); }
template<int N> __device__ __forceinline__ void cp_wait() {
    asm volatile("cp.async.wait_group %0;\n" :: "n"(N));
}

__device__ __forceinline__ void ldsm4(unsigned r[4], uint32_t addr) {
    asm volatile("ldmatrix.sync.aligned.m8n8.x4.shared.b16 {%0,%1,%2,%3}, [%4];"
                 : "=r"(r[0]), "=r"(r[1]), "=r"(r[2]), "=r"(r[3]) : "r"(addr));
}

template<int DT>
__device__ __forceinline__ void mma2(float c[4], const unsigned a[4], const unsigned b[2]) {
    if (DT == 0)
        asm volatile(
            "mma.sync.aligned.m16n8k16.row.col.f32.bf16.bf16.f32 "
            "{%0,%1,%2,%3},{%4,%5,%6,%7},{%8,%9},{%0,%1,%2,%3};\n"
            : "+f"(c[0]), "+f"(c[1]), "+f"(c[2]), "+f"(c[3])
            : "r"(a[0]), "r"(a[1]), "r"(a[2]), "r"(a[3]), "r"(b[0]), "r"(b[1]));
    else
        asm volatile(
            "mma.sync.aligned.m16n8k16.row.col.f32.f16.f16.f32 "
            "{%0,%1,%2,%3},{%4,%5,%6,%7},{%8,%9},{%0,%1,%2,%3};\n"
            : "+f"(c[0]), "+f"(c[1]), "+f"(c[2]), "+f"(c[3])
            : "r"(a[0]), "r"(a[1]), "r"(a[2]), "r"(a[3]), "r"(b[0]), "r"(b[1]));
}

// ---------------- pipelined NT GEMM with ldmatrix fragments ----------------
// C[M][N] = sum_k A[m,k]*B[n,k]; A versions = 1+ASPL (hi[,lo]), B = 1+BSPL.
// Passes: hi*hi (+ hi*lo if BSPL) (+ lo*hi if ASPL). fp32 accum.
// DT: 0 bf16, 1 fp16. OUTM: 0 fp32, 1 split bf16, 2 split fp16.
// BIASM: 0 none, 1 bias[row], 2 bias[col].
template<int DT, int ASPL, int BSPL, int OUTM, int BIASM, int WM_, int WN_, int BM, int BN>
__global__ __launch_bounds__(256)
void gemm_pl(const void* __restrict__ Ahi_, const void* __restrict__ Alo_,
             const void* __restrict__ Bhi_, const void* __restrict__ Blo_,
             const float* __restrict__ bias,
             void* __restrict__ C0, void* __restrict__ C1,
             int M, int N, int K,
             long long sA, long long sB, long long sC) {
    constexpr int NPA = 1 + ASPL, NPB = 1 + BSPL;
    constexpr int FM = BM / (16 * WM_), FN = BN / (8 * WN_);
    constexpr int ABYT = BM * SPAD * 2;      // bytes per A version per stage
    constexpr int BBYT = BN * SPAD * 2;
    constexpr int SSB = NPA * ABYT + NPB * BBYT;  // stage bytes
    extern __shared__ char sh[];
    const uint32_t sbase = smem_u32(sh);

    const int bz = blockIdx.z;
    const unsigned short* Ah = (const unsigned short*)Ahi_ + (size_t)bz * sA;
    const unsigned short* Al = (const unsigned short*)Alo_ + (size_t)bz * sA;
    const unsigned short* Bh = (const unsigned short*)Bhi_ + (size_t)bz * sB;
    const unsigned short* Bl = (const unsigned short*)Blo_ + (size_t)bz * sB;

    const int m0 = blockIdx.y * BM, n0 = blockIdx.x * BN;
    const int tid = threadIdx.x, warp = tid >> 5, lane = tid & 31;
    const int wm = warp / WN_, wn = warp % WN_;
    const int grp = lane >> 2, qid = lane & 3;

    // ldmatrix per-lane byte offsets
    const int r8 = lane & 7, mi = lane >> 3;
    const uint32_t aLane = (uint32_t)(((r8 + ((mi & 1) << 3)) * SPAD + ((mi >> 1) << 3)) * 2);
    const uint32_t bLane = (uint32_t)(((r8 + ((mi >> 1) << 3)) * SPAD + ((mi & 1) << 3)) * 2);

    float acc[FM][FN][4] = {};

    auto load_stage = [&](int st, int kt) {
        #pragma unroll
        for (int v = 0; v < NPA; v++) {
            const unsigned short* g = v ? Al : Ah;
            uint32_t base = sbase + st * SSB + v * ABYT;
            #pragma unroll
            for (int cid = tid; cid < BM * 4; cid += 256) {
                int row = cid >> 2, seg = cid & 3;
                cp16(base + (uint32_t)((row * SPAD + seg * 8) * 2),
                     g + (size_t)(m0 + row) * K + kt + seg * 8);
            }
        }
        #pragma unroll
        for (int v = 0; v < NPB; v++) {
            const unsigned short* g = v ? Bl : Bh;
            uint32_t base = sbase + st * SSB + NPA * ABYT + v * BBYT;
            #pragma unroll
            for (int cid = tid; cid < BN * 4; cid += 256) {
                int row = cid >> 2, seg = cid & 3;
                cp16(base + (uint32_t)((row * SPAD + seg * 8) * 2),
                     g + (size_t)(n0 + row) * K + kt + seg * 8);
            }
        }
    };

    load_stage(0, 0);
    cp_commit();

    const int KT = K / 32;
    for (int it = 0; it < KT; ++it) {
        const int st = it & 1;
        if (it + 1 < KT) {
            load_stage(st ^ 1, (it + 1) * 32);
            cp_commit();
            cp_wait<1>();
        } else {
            cp_wait<0>();
        }
        __syncthreads();

        const uint32_t sA0 = sbase + st * SSB;
        const uint32_t sA1 = sA0 + ABYT;
        const uint32_t sB0 = sbase + st * SSB + NPA * ABYT;
        const uint32_t sB1 = sB0 + BBYT;

        #pragma unroll
        for (int kk = 0; kk < 2; kk++) {
            const uint32_t koff = kk * 32;   // 16 elems * 2B
            unsigned a[FM][4], b0[FN][2], b1[FN][2];
            // B fragments (hi, and lo if BSPL) via ldmatrix x4 (two n8 tiles each)
            #pragma unroll
            for (int nn2 = 0; nn2 < FN / 2; nn2++) {
                uint32_t boff = bLane + (uint32_t)((wn * FN * 8 + nn2 * 16) * SPAD * 2) + koff;
                ldsm4(&b0[2 * nn2][0], sB0 + boff);
                if (BSPL) ldsm4(&b1[2 * nn2][0], sB1 + boff);
            }
            // A hi fragments
            #pragma unroll
            for (int mm = 0; mm < FM; mm++) {
                uint32_t aoff = aLane + (uint32_t)((wm * FM * 16 + mm * 16) * SPAD * 2) + koff;
                ldsm4(a[mm], sA0 + aoff);
            }
            #pragma unroll
            for (int mm = 0; mm < FM; mm++)
                #pragma unroll
                for (int nn = 0; nn < FN; nn++) {
                    mma2<DT>(acc[mm][nn], a[mm], b0[nn]);
                    if (BSPL) mma2<DT>(acc[mm][nn], a[mm], b1[nn]);
                }
            if (ASPL) {
                #pragma unroll
                for (int mm = 0; mm < FM; mm++) {
                    uint32_t aoff = aLane + (uint32_t)((wm * FM * 16 + mm * 16) * SPAD * 2) + koff;
                    ldsm4(a[mm], sA1 + aoff);
                }
                #pragma unroll
                for (int mm = 0; mm < FM; mm++)
                    #pragma unroll
                    for (int nn = 0; nn < FN; nn++)
                        mma2<DT>(acc[mm][nn], a[mm], b0[nn]);
            }
        }
        __syncthreads();
    }

    // epilogue: vectorized pair stores (cols qid*2, qid*2+1)
    #pragma unroll
    for (int mm = 0; mm < FM; mm++) {
        #pragma unroll
        for (int nn = 0; nn < FN; nn++) {
            #pragma unroll
            for (int half = 0; half < 2; half++) {
                int row = m0 + wm * (FM * 16) + mm * 16 + grp + half * 8;
                int col = n0 + wn * (FN * 8) + nn * 8 + qid * 2;
                float v0 = acc[mm][nn][half * 2 + 0];
                float v1 = acc[mm][nn][half * 2 + 1];
                if (BIASM == 1) { float bb = bias[row]; v0 += bb; v1 += bb; }
                if (BIASM == 2) { v0 += bias[col]; v1 += bias[col + 1]; }
                size_t off = (size_t)bz * sC + (size_t)row * N + col;
                if (OUTM == 0) {
                    float2 p; p.x = v0; p.y = v1;
                    *(float2*)((float*)C0 + off) = p;
                } else if (OUTM == 1) {
                    bf16 h0 = __float2bfloat16(v0), h1 = __float2bfloat16(v1);
                    bf16 l0 = __float2bfloat16(v0 - __bfloat162float(h0));
                    bf16 l1 = __float2bfloat16(v1 - __bfloat162float(h1));
                    __nv_bfloat162 hp; hp.x = h0; hp.y = h1;
                    __nv_bfloat162 lp; lp.x = l0; lp.y = l1;
                    *(__nv_bfloat162*)((bf16*)C0 + off) = hp;
                    *(__nv_bfloat162*)((bf16*)C1 + off) = lp;
                } else {
                    f16 h0 = __float2half_rn(v0), h1 = __float2half_rn(v1);
                    f16 l0 = __float2half_rn(v0 - __half2float(h0));
                    f16 l1 = __float2half_rn(v1 - __half2float(h1));
                    __half2 hp; hp.x = h0; hp.y = h1;
                    __half2 lp; lp.x = l0; lp.y = l1;
                    *(__half2*)((f16*)C0 + off) = hp;
                    *(__half2*)((f16*)C1 + off) = lp;
                }
            }
        }
    }
}

// ------- fused f-assembly + softmax, register-resident, P -> fp16 -------
__device__ __forceinline__ int refl(int i) {
    return i < 0 ? -i : (i > 63 ? 126 - i : i);
}

__global__ __launch_bounds__(256)
void attn_softmax_kernel(const float* __restrict__ scale) {
    const int l = blockIdx.x;
    const int b = blockIdx.y;
    const int tid = threadIdx.x;
    const int il = l >> 6, jl = l & 63;

    __shared__ float red[256];

    const float* Gb = d_G + (size_t)b * HWH * HWH;
    const float* gr[9];
    float s2[9];
    #pragma unroll
    for (int k = 0; k < 9; k++) {
        int di = k / 3, dj = k % 3;
        gr[k] = Gb + (size_t)(refl(il + di - 1) * 64 + refl(jl + dj - 1)) * HWH;
        float s = scale[k];
        s2[k] = s * s;
    }

    float v[16];
    float mx = -3.4e38f;
    #pragma unroll
    for (int i = 0; i < 16; i++) {
        int m = tid + i * 256;
        int im = m >> 6, jm = m & 63;
        float acc = 0.f;
        #pragma unroll
        for (int di = 0; di < 3; di++) {
            int ci = refl(im + di - 1) * 64;
            #pragma unroll
            for (int dj = 0; dj < 3; dj++)
                acc += s2[di * 3 + dj] * gr[di * 3 + dj][ci + refl(jm + dj - 1)];
        }
        v[i] = acc;
        mx = fmaxf(mx, acc);
    }
    red[tid] = mx; __syncthreads();
    for (int st = 128; st > 0; st >>= 1) {
        if (tid < st) red[tid] = fmaxf(red[tid], red[tid + st]);
        __syncthreads();
    }
    mx = red[0];
    __syncthreads();

    float sum = 0.f;
    #pragma unroll
    for (int i = 0; i < 16; i++) {
        v[i] = __expf(v[i] - mx);
        sum += v[i];
    }
    red[tid] = sum; __syncthreads();
    for (int st = 128; st > 0; st >>= 1) {
        if (tid < st) red[tid] += red[tid + st];
        __syncthreads();
    }
    float inv = 1.f / red[0];

    f16* pr = d_P + ((size_t)b * HWH + l) * HWH;
    #pragma unroll
    for (int i = 0; i < 16; i++)
        pr[tid + i * 256] = __float2half_rn(v[i] * inv);
}

// ---------------- host ----------------
#define SYM(p, s) do { void* _t; cudaGetSymbolAddress(&_t, s); p = (decltype(p))_t; } while (0)

#define LAUNCH_GEMM(DT, ASPL, BSPL, OUTM, BIASM, WM, WN, BM, BN, Ah, Al, Bh, Bl, bias, C0, C1, M, N, K, sa, sb, sc) \
    do { \
        auto kfn = gemm_pl<DT, ASPL, BSPL, OUTM, BIASM, WM, WN, BM, BN>; \
        int smemB = 2 * ((1 + ASPL) * (BM) + (1 + BSPL) * (BN)) * SPAD * 2; \
        cudaFuncSetAttribute(kfn, cudaFuncAttributeMaxDynamicSharedMemorySize, smemB); \
        kfn<<<dim3((N) / (BN), (M) / (BM), BB), 256, smemB>>>( \
            Ah, Al, Bh, Bl, bias, C0, C1, M, N, K, sa, sb, sc); \
    } while (0)

extern "C" void kernel_launch(void* const* d_in, const int* in_sizes, int n_in,
                              void* d_out, int out_size) {
    (void)in_sizes; (void)n_in; (void)out_size;
    const float* content = (const float*)d_in[0];
    const float* style   = (const float*)d_in[1];
    const float* fusion  = (const float*)d_in[2];
    const float* theta_b = (const float*)d_in[4];
    const float* phi_b   = (const float*)d_in[6];
    const float* g_b     = (const float*)d_in[8];
    const float* W_b     = (const float*)d_in[10];
    const float* scale   = (const float*)d_in[11];
    float* out = (float*)d_out;

    bf16 *xnT_hi, *xnT_lo, *snT_hi, *snT_lo, *fsT_hi, *fsT_lo;
    bf16 *thw_hi, *thw_lo, *phw_hi, *phw_lo, *gw_hi, *gw_lo, *Ww_hi, *Ww_lo;
    bf16 *thT_hi, *thT_lo, *phT_hi, *phT_lo;
    f16 *gT_hi, *gT_lo, *Pp;
    bf16 *y_hi, *y_lo;
    float* Gp;
    SYM(xnT_hi, d_xnT_hi); SYM(xnT_lo, d_xnT_lo);
    SYM(snT_hi, d_snT_hi); SYM(snT_lo, d_snT_lo);
    SYM(fsT_hi, d_fsT_hi); SYM(fsT_lo, d_fsT_lo);
    SYM(thw_hi, d_thw_hi); SYM(thw_lo, d_thw_lo);
    SYM(phw_hi, d_phw_hi); SYM(phw_lo, d_phw_lo);
    SYM(gw_hi,  d_gw_hi);  SYM(gw_lo,  d_gw_lo);
    SYM(Ww_hi,  d_Ww_hi);  SYM(Ww_lo,  d_Ww_lo);
    SYM(thT_hi, d_thT_hi); SYM(thT_lo, d_thT_lo);
    SYM(phT_hi, d_phT_hi); SYM(phT_lo, d_phT_lo);
    SYM(gT_hi,  d_gT_hi);  SYM(gT_lo,  d_gT_lo);
    SYM(Pp,     d_P);
    SYM(y_hi,   d_y_hi);   SYM(y_lo,   d_y_lo);
    SYM(Gp,     d_G);

    // 1) instance-norm stats
    stats_kernel<<<2 * BB * CC, 256>>>(content, style);
    // 2) normalize + transpose + split
    norm_split_T<<<dim3(HWH / 32, CC / 32, 3 * BB), dim3(32, 8)>>>(content, style, fusion);
    // 3) weight splits
    weight_split<<<(ICI * CC) / 256, 256>>>((const float*)d_in[3], (const float*)d_in[5],
                                            (const float*)d_in[7], (const float*)d_in[9]);

    // 4) theta_xT = xnT @ theta_w^T + theta_b : M=4096, N=256, K=512
    LAUNCH_GEMM(0, 1, 1, 1, 2, 4, 2, 128, 64,
                xnT_hi, xnT_lo, thw_hi, thw_lo, theta_b, thT_hi, thT_lo,
                HWH, ICI, CC, (long long)HWH * CC, 0LL, (long long)HWH * ICI);

    // 5) phi_sT = snT @ phi_w^T + phi_b
    LAUNCH_GEMM(0, 1, 1, 1, 2, 4, 2, 128, 64,
                snT_hi, snT_lo, phw_hi, phw_lo, phi_b, phT_hi, phT_lo,
                HWH, ICI, CC, (long long)HWH * CC, 0LL, (long long)HWH * ICI);

    // 6) g_sT = g_w @ fsT^T + g_b : M=256, N=4096, K=512 -> split fp16
    LAUNCH_GEMM(0, 1, 1, 2, 1, 4, 2, 128, 64,
                gw_hi, gw_lo, fsT_hi, fsT_lo, g_b, gT_hi, gT_lo,
                ICI, HWH, CC, 0LL, (long long)HWH * CC, (long long)ICI * HWH);

    // 7) G = theta_xT @ phi_sT^T : M=N=4096, K=256 -> fp32
    LAUNCH_GEMM(0, 1, 1, 0, 0, 2, 4, 128, 128,
                thT_hi, thT_lo, phT_hi, phT_lo, (const float*)nullptr, Gp, (void*)nullptr,
                HWH, HWH, ICI, (long long)HWH * ICI, (long long)HWH * ICI, (long long)HWH * HWH);

    // 8) gather + softmax -> P (fp16)
    attn_softmax_kernel<<<dim3(HWH, BB), 256>>>(scale);

    // 9) y = P @ g_s : M=4096, N=256, K=4096, fp16 single A x split B (BN=128 halves P re-reads)
    LAUNCH_GEMM(1, 0, 1, 1, 0, 2, 4, 128, 128,
                Pp, Pp, gT_hi, gT_lo, (const float*)nullptr, y_hi, y_lo,
                HWH, ICI, HWH, (long long)HWH * HWH, (long long)ICI * HWH, (long long)HWH * ICI);

    // 10) out = W_w @ y^T + W_b : M=512, N=4096, K=256 -> fp32
    LAUNCH_GEMM(0, 1, 1, 0, 1, 2, 4, 128, 128,
                Ww_hi, Ww_lo, y_hi, y_lo, W_b, out, (void*)nullptr,
                CC, HWH, ICI, 0LL, (long long)HWH * ICI, (long long)CC * HWH);
}

// round 10
// speedup vs baseline: 1.4829x; 1.0111x over previous
#include <cuda_runtime.h>
#include <cuda_bf16.h>
#include <cuda_fp16.h>
#include <math.h>
#include <stdint.h>

typedef __nv_bfloat16 bf16;
typedef __half f16;

#define BB   2
#define CC   512
#define HWH  4096
#define ICI  256
#define SPAD 40

// ---------------- scratch ----------------
__device__ float d_mean[2 * BB * CC];
__device__ float d_istd[2 * BB * CC];

__device__ bf16 d_xnT_hi[(size_t)BB * HWH * CC];
__device__ bf16 d_xnT_lo[(size_t)BB * HWH * CC];
__device__ bf16 d_snT_hi[(size_t)BB * HWH * CC];
__device__ bf16 d_snT_lo[(size_t)BB * HWH * CC];
__device__ bf16 d_fsT_hi[(size_t)BB * HWH * CC];
__device__ bf16 d_fsT_lo[(size_t)BB * HWH * CC];

__device__ bf16 d_thw_hi[ICI * CC], d_thw_lo[ICI * CC];
__device__ bf16 d_phw_hi[ICI * CC], d_phw_lo[ICI * CC];
__device__ bf16 d_gw_hi [ICI * CC], d_gw_lo [ICI * CC];
__device__ bf16 d_Ww_hi [CC * ICI], d_Ww_lo [CC * ICI];

__device__ bf16 d_thT_hi[(size_t)BB * HWH * ICI];
__device__ bf16 d_thT_lo[(size_t)BB * HWH * ICI];
__device__ bf16 d_phT_hi[(size_t)BB * HWH * ICI];
__device__ bf16 d_phT_lo[(size_t)BB * HWH * ICI];

__device__ f16 d_gT_hi[(size_t)BB * ICI * HWH];
__device__ f16 d_gT_lo[(size_t)BB * ICI * HWH];

__device__ float d_G[(size_t)BB * HWH * HWH];

__device__ f16 d_P[(size_t)BB * HWH * HWH];

__device__ bf16 d_y_hi[(size_t)BB * HWH * ICI];
__device__ bf16 d_y_lo[(size_t)BB * HWH * ICI];

// ------------- stats -------------
__global__ void stats_kernel(const float* __restrict__ content,
                             const float* __restrict__ style) {
    int idx = blockIdx.x;
    int which = idx >> 10;
    int bc = idx & 1023;
    const float* src = (which == 0 ? content : style) + (size_t)bc * HWH;
    double s = 0.0, s2 = 0.0;
    for (int i = threadIdx.x; i < HWH; i += 256) {
        float v = src[i];
        s += v; s2 += (double)v * v;
    }
    __shared__ double sh1[256], sh2[256];
    sh1[threadIdx.x] = s; sh2[threadIdx.x] = s2;
    __syncthreads();
    for (int st = 128; st > 0; st >>= 1) {
        if (threadIdx.x < st) {
            sh1[threadIdx.x] += sh1[threadIdx.x + st];
            sh2[threadIdx.x] += sh2[threadIdx.x + st];
        }
        __syncthreads();
    }
    if (threadIdx.x == 0) {
        double mean = sh1[0] / (double)HWH;
        double var = (sh2[0] - (double)HWH * mean * mean) / (double)(HWH - 1);
        d_mean[idx] = (float)mean;
        d_istd[idx] = (float)(1.0 / sqrt(var + 1e-5));
    }
}

// ------ normalize + transpose + split ------
__global__ void norm_split_T(const float* __restrict__ content,
                             const float* __restrict__ style,
                             const float* __restrict__ fusion) {
    int zz = blockIdx.z;
    int src = zz >> 1, b = zz & 1;
    const float* in;
    bf16 *oh, *ol;
    if (src == 0)      { in = content; oh = d_xnT_hi; ol = d_xnT_lo; }
    else if (src == 1) { in = style;   oh = d_snT_hi; ol = d_snT_lo; }
    else               { in = fusion;  oh = d_fsT_hi; ol = d_fsT_lo; }
    in += (size_t)b * CC * HWH;
    oh += (size_t)b * HWH * CC;
    ol += (size_t)b * HWH * CC;

    int p0 = blockIdx.x * 32, c0 = blockIdx.y * 32;
    __shared__ float tile[32][33];
    int tx = threadIdx.x, ty = threadIdx.y;
    #pragma unroll
    for (int i = 0; i < 4; i++) {
        int c = c0 + ty + i * 8;
        float v = in[(size_t)c * HWH + p0 + tx];
        if (src < 2) {
            int mi = src * 1024 + b * 512 + c;
            v = (v - d_mean[mi]) * d_istd[mi];
        }
        tile[ty + i * 8][tx] = v;
    }
    __syncthreads();
    #pragma unroll
    for (int i = 0; i < 4; i++) {
        int p = p0 + ty + i * 8;
        int c = c0 + tx;
        float v = tile[tx][ty + i * 8];
        bf16 h = __float2bfloat16(v);
        size_t off = (size_t)p * CC + c;
        oh[off] = h;
        ol[off] = __float2bfloat16(v - __bfloat162float(h));
    }
}

// ------------- weight split -------------
__global__ void weight_split(const float* __restrict__ tw, const float* __restrict__ pw,
                             const float* __restrict__ gw, const float* __restrict__ Ww) {
    int i = blockIdx.x * 256 + threadIdx.x;
    if (i >= ICI * CC) return;
    float v; bf16 h;
    v = tw[i]; h = __float2bfloat16(v); d_thw_hi[i] = h; d_thw_lo[i] = __float2bfloat16(v - __bfloat162float(h));
    v = pw[i]; h = __float2bfloat16(v); d_phw_hi[i] = h; d_phw_lo[i] = __float2bfloat16(v - __bfloat162float(h));
    v = gw[i]; h = __float2bfloat16(v); d_gw_hi[i]  = h; d_gw_lo[i]  = __float2bfloat16(v - __bfloat162float(h));
    v = Ww[i]; h = __float2bfloat16(v); d_Ww_hi[i]  = h; d_Ww_lo[i]  = __float2bfloat16(v - __bfloat162float(h));
}

// ---------------- low-level helpers ----------------
__device__ __forceinline__ uint32_t smem_u32(const void* p) {
    uint32_t a;
    asm("{ .reg .u64 t; cvta.to.shared.u64 t, %1; cvt.u32.u64 %0, t; }"
        : "=r"(a) : "l"(p));
    return a;
}

__device__ __forceinline__ void cp16(uint32_t dst, const void* src) {
    asm volatile("cp.async.cg.shared.global [%0], [%1], 16;\n" :: "r"(dst), "l"(src));
}
__device__ __forceinline__ void cp_commit() { asm volatile("cp.async.commit_group;\n"); }
template<int N> __device__ __forceinline__ void cp_wait() {
    asm volatile("cp.async.wait_group %0;\n" :: "n"(N));
}

__device__ __forceinline__ void ldsm4(unsigned r[4], uint32_t addr) {
    asm volatile("ldmatrix.sync.aligned.m8n8.x4.shared.b16 {%0,%1,%2,%3}, [%4];"
                 : "=r"(r[0]), "=r"(r[1]), "=r"(r[2]), "=r"(r[3]) : "r"(addr));
}

template<int DT>
__device__ __forceinline__ void mma2(float c[4], const unsigned a[4], const unsigned b[2]) {
    if (DT == 0)
        asm volatile(
            "mma.sync.aligned.m16n8k16.row.col.f32.bf16.bf16.f32 "
            "{%0,%1,%2,%3},{%4,%5,%6,%7},{%8,%9},{%0,%1,%2,%3};\n"
            : "+f"(c[0]), "+f"(c[1]), "+f"(c[2]), "+f"(c[3])
            : "r"(a[0]), "r"(a[1]), "r"(a[2]), "r"(a[3]), "r"(b[0]), "r"(b[1]));
    else
        asm volatile(
            "mma.sync.aligned.m16n8k16.row.col.f32.f16.f16.f32 "
            "{%0,%1,%2,%3},{%4,%5,%6,%7},{%8,%9},{%0,%1,%2,%3};\n"
            : "+f"(c[0]), "+f"(c[1]), "+f"(c[2]), "+f"(c[3])
            : "r"(a[0]), "r"(a[1]), "r"(a[2]), "r"(a[3]), "r"(b[0]), "r"(b[1]));
}

// ---------------- pipelined NT GEMM: NST stages, ONE sync per K-iter ----------------
// C[M][N] = sum_k A[m,k]*B[n,k]; A versions = 1+ASPL (hi[,lo]), B = 1+BSPL.
// Passes: hi*hi (+ hi*lo if BSPL) (+ lo*hi if ASPL). fp32 accum.
// DT: 0 bf16, 1 fp16. OUTM: 0 fp32, 1 split bf16, 2 split fp16.
// BIASM: 0 none, 1 bias[row], 2 bias[col].
template<int DT, int ASPL, int BSPL, int OUTM, int BIASM, int WM_, int WN_, int BM, int BN, int NST>
__global__ __launch_bounds__(256)
void gemm_pl(const void* __restrict__ Ahi_, const void* __restrict__ Alo_,
             const void* __restrict__ Bhi_, const void* __restrict__ Blo_,
             const float* __restrict__ bias,
             void* __restrict__ C0, void* __restrict__ C1,
             int M, int N, int K,
             long long sA, long long sB, long long sC) {
    constexpr int NPA = 1 + ASPL, NPB = 1 + BSPL;
    constexpr int FM = BM / (16 * WM_), FN = BN / (8 * WN_);
    constexpr int ABYT = BM * SPAD * 2;
    constexpr int BBYT = BN * SPAD * 2;
    constexpr int SSB = NPA * ABYT + NPB * BBYT;   // bytes per stage
    extern __shared__ char sh[];
    const uint32_t sbase = smem_u32(sh);

    const int bz = blockIdx.z;
    const unsigned short* Ah = (const unsigned short*)Ahi_ + (size_t)bz * sA;
    const unsigned short* Al = (const unsigned short*)Alo_ + (size_t)bz * sA;
    const unsigned short* Bh = (const unsigned short*)Bhi_ + (size_t)bz * sB;
    const unsigned short* Bl = (const unsigned short*)Blo_ + (size_t)bz * sB;

    const int m0 = blockIdx.y * BM, n0 = blockIdx.x * BN;
    const int tid = threadIdx.x, warp = tid >> 5, lane = tid & 31;
    const int wm = warp / WN_, wn = warp % WN_;
    const int grp = lane >> 2, qid = lane & 3;

    const int r8 = lane & 7, mi = lane >> 3;
    const uint32_t aLane = (uint32_t)(((r8 + ((mi & 1) << 3)) * SPAD + ((mi >> 1) << 3)) * 2);
    const uint32_t bLane = (uint32_t)(((r8 + ((mi >> 1) << 3)) * SPAD + ((mi & 1) << 3)) * 2);

    float acc[FM][FN][4] = {};

    auto load_stage = [&](int st, int kt) {
        #pragma unroll
        for (int v = 0; v < NPA; v++) {
            const unsigned short* g = v ? Al : Ah;
            uint32_t base = sbase + st * SSB + v * ABYT;
            #pragma unroll
            for (int cid = tid; cid < BM * 4; cid += 256) {
                int row = cid >> 2, seg = cid & 3;
                cp16(base + (uint32_t)((row * SPAD + seg * 8) * 2),
                     g + (size_t)(m0 + row) * K + kt + seg * 8);
            }
        }
        #pragma unroll
        for (int v = 0; v < NPB; v++) {
            const unsigned short* g = v ? Bl : Bh;
            uint32_t base = sbase + st * SSB + NPA * ABYT + v * BBYT;
            #pragma unroll
            for (int cid = tid; cid < BN * 4; cid += 256) {
                int row = cid >> 2, seg = cid & 3;
                cp16(base + (uint32_t)((row * SPAD + seg * 8) * 2),
                     g + (size_t)(n0 + row) * K + kt + seg * 8);
            }
        }
    };

    const int KT = K / 32;
    // prologue: NST-1 stages in flight
    #pragma unroll
    for (int p = 0; p < NST - 1; p++) {
        if (p < KT) { load_stage(p, p * 32); cp_commit(); }
    }

    for (int it = 0; it < KT; ++it) {
        const int st = it % NST;
        // wait for the oldest stage (st); exact tail handling
        if (KT - 1 - it >= NST - 2) cp_wait<(NST >= 2 ? NST - 2 : 0)>();
        else                        cp_wait<0>();
        __syncthreads();   // single barrier: stage st ready AND stage (it+NST-1)%NST free

        const int nx = it + NST - 1;
        if (nx < KT) { load_stage(nx % NST, nx * 32); cp_commit(); }

        const uint32_t sA0 = sbase + st * SSB;
        const uint32_t sA1 = sA0 + ABYT;
        const uint32_t sB0 = sbase + st * SSB + NPA * ABYT;
        const uint32_t sB1 = sB0 + BBYT;

        #pragma unroll
        for (int kk = 0; kk < 2; kk++) {
            const uint32_t koff = kk * 32;
            unsigned a[FM][4], b0[FN][2], b1[FN][2];
            #pragma unroll
            for (int nn2 = 0; nn2 < FN / 2; nn2++) {
                uint32_t boff = bLane + (uint32_t)((wn * FN * 8 + nn2 * 16) * SPAD * 2) + koff;
                ldsm4(&b0[2 * nn2][0], sB0 + boff);
                if (BSPL) ldsm4(&b1[2 * nn2][0], sB1 + boff);
            }
            #pragma unroll
            for (int mm = 0; mm < FM; mm++) {
                uint32_t aoff = aLane + (uint32_t)((wm * FM * 16 + mm * 16) * SPAD * 2) + koff;
                ldsm4(a[mm], sA0 + aoff);
            }
            #pragma unroll
            for (int mm = 0; mm < FM; mm++)
                #pragma unroll
                for (int nn = 0; nn < FN; nn++) {
                    mma2<DT>(acc[mm][nn], a[mm], b0[nn]);
                    if (BSPL) mma2<DT>(acc[mm][nn], a[mm], b1[nn]);
                }
            if (ASPL) {
                #pragma unroll
                for (int mm = 0; mm < FM; mm++) {
                    uint32_t aoff = aLane + (uint32_t)((wm * FM * 16 + mm * 16) * SPAD * 2) + koff;
                    ldsm4(a[mm], sA1 + aoff);
                }
                #pragma unroll
                for (int mm = 0; mm < FM; mm++)
                    #pragma unroll
                    for (int nn = 0; nn < FN; nn++)
                        mma2<DT>(acc[mm][nn], a[mm], b0[nn]);
            }
        }
        // no second barrier: next overwrite of any buffer is gated by the
        // single barrier at the top of the iteration that writes it.
    }

    // epilogue: vectorized pair stores
    #pragma unroll
    for (int mm = 0; mm < FM; mm++) {
        #pragma unroll
        for (int nn = 0; nn < FN; nn++) {
            #pragma unroll
            for (int half = 0; half < 2; half++) {
                int row = m0 + wm * (FM * 16) + mm * 16 + grp + half * 8;
                int col = n0 + wn * (FN * 8) + nn * 8 + qid * 2;
                float v0 = acc[mm][nn][half * 2 + 0];
                float v1 = acc[mm][nn][half * 2 + 1];
                if (BIASM == 1) { float bb = bias[row]; v0 += bb; v1 += bb; }
                if (BIASM == 2) { v0 += bias[col]; v1 += bias[col + 1]; }
                size_t off = (size_t)bz * sC + (size_t)row * N + col;
                if (OUTM == 0) {
                    float2 p; p.x = v0; p.y = v1;
                    *(float2*)((float*)C0 + off) = p;
                } else if (OUTM == 1) {
                    bf16 h0 = __float2bfloat16(v0), h1 = __float2bfloat16(v1);
                    bf16 l0 = __float2bfloat16(v0 - __bfloat162float(h0));
                    bf16 l1 = __float2bfloat16(v1 - __bfloat162float(h1));
                    __nv_bfloat162 hp; hp.x = h0; hp.y = h1;
                    __nv_bfloat162 lp; lp.x = l0; lp.y = l1;
                    *(__nv_bfloat162*)((bf16*)C0 + off) = hp;
                    *(__nv_bfloat162*)((bf16*)C1 + off) = lp;
                } else {
                    f16 h0 = __float2half_rn(v0), h1 = __float2half_rn(v1);
                    f16 l0 = __float2half_rn(v0 - __half2float(h0));
                    f16 l1 = __float2half_rn(v1 - __half2float(h1));
                    __half2 hp; hp.x = h0; hp.y = h1;
                    __half2 lp; lp.x = l0; lp.y = l1;
                    *(__half2*)((f16*)C0 + off) = hp;
                    *(__half2*)((f16*)C1 + off) = lp;
                }
            }
        }
    }
}

// ------- fused f-assembly + softmax, register-resident, P -> fp16 -------
__device__ __forceinline__ int refl(int i) {
    return i < 0 ? -i : (i > 63 ? 126 - i : i);
}

__global__ __launch_bounds__(256)
void attn_softmax_kernel(const float* __restrict__ scale) {
    const int l = blockIdx.x;
    const int b = blockIdx.y;
    const int tid = threadIdx.x;
    const int il = l >> 6, jl = l & 63;

    __shared__ float red[256];

    const float* Gb = d_G + (size_t)b * HWH * HWH;
    const float* gr[9];
    float s2[9];
    #pragma unroll
    for (int k = 0; k < 9; k++) {
        int di = k / 3, dj = k % 3;
        gr[k] = Gb + (size_t)(refl(il + di - 1) * 64 + refl(jl + dj - 1)) * HWH;
        float s = scale[k];
        s2[k] = s * s;
    }

    float v[16];
    float mx = -3.4e38f;
    #pragma unroll
    for (int i = 0; i < 16; i++) {
        int m = tid + i * 256;
        int im = m >> 6, jm = m & 63;
        float acc = 0.f;
        #pragma unroll
        for (int di = 0; di < 3; di++) {
            int ci = refl(im + di - 1) * 64;
            #pragma unroll
            for (int dj = 0; dj < 3; dj++)
                acc += s2[di * 3 + dj] * gr[di * 3 + dj][ci + refl(jm + dj - 1)];
        }
        v[i] = acc;
        mx = fmaxf(mx, acc);
    }
    red[tid] = mx; __syncthreads();
    for (int st = 128; st > 0; st >>= 1) {
        if (tid < st) red[tid] = fmaxf(red[tid], red[tid + st]);
        __syncthreads();
    }
    mx = red[0];
    __syncthreads();

    float sum = 0.f;
    #pragma unroll
    for (int i = 0; i < 16; i++) {
        v[i] = __expf(v[i] - mx);
        sum += v[i];
    }
    red[tid] = sum; __syncthreads();
    for (int st = 128; st > 0; st >>= 1) {
        if (tid < st) red[tid] += red[tid + st];
        __syncthreads();
    }
    float inv = 1.f / red[0];

    f16* pr = d_P + ((size_t)b * HWH + l) * HWH;
    #pragma unroll
    for (int i = 0; i < 16; i++)
        pr[tid + i * 256] = __float2half_rn(v[i] * inv);
}

// ---------------- host ----------------
#define SYM(p, s) do { void* _t; cudaGetSymbolAddress(&_t, s); p = (decltype(p))_t; } while (0)

#define LAUNCH_GEMM(DT, ASPL, BSPL, OUTM, BIASM, WM, WN, BM, BN, NST, Ah, Al, Bh, Bl, bias, C0, C1, M, N, K, sa, sb, sc) \
    do { \
        auto kfn = gemm_pl<DT, ASPL, BSPL, OUTM, BIASM, WM, WN, BM, BN, NST>; \
        int smemB = (NST) * ((1 + ASPL) * (BM) + (1 + BSPL) * (BN)) * SPAD * 2; \
        cudaFuncSetAttribute(kfn, cudaFuncAttributeMaxDynamicSharedMemorySize, smemB); \
        kfn<<<dim3((N) / (BN), (M) / (BM), BB), 256, smemB>>>( \
            Ah, Al, Bh, Bl, bias, C0, C1, M, N, K, sa, sb, sc); \
    } while (0)

extern "C" void kernel_launch(void* const* d_in, const int* in_sizes, int n_in,
                              void* d_out, int out_size) {
    (void)in_sizes; (void)n_in; (void)out_size;
    const float* content = (const float*)d_in[0];
    const float* style   = (const float*)d_in[1];
    const float* fusion  = (const float*)d_in[2];
    const float* theta_b = (const float*)d_in[4];
    const float* phi_b   = (const float*)d_in[6];
    const float* g_b     = (const float*)d_in[8];
    const float* W_b     = (const float*)d_in[10];
    const float* scale   = (const float*)d_in[11];
    float* out = (float*)d_out;

    bf16 *xnT_hi, *xnT_lo, *snT_hi, *snT_lo, *fsT_hi, *fsT_lo;
    bf16 *thw_hi, *thw_lo, *phw_hi, *phw_lo, *gw_hi, *gw_lo, *Ww_hi, *Ww_lo;
    bf16 *thT_hi, *thT_lo, *phT_hi, *phT_lo;
    f16 *gT_hi, *gT_lo, *Pp;
    bf16 *y_hi, *y_lo;
    float* Gp;
    SYM(xnT_hi, d_xnT_hi); SYM(xnT_lo, d_xnT_lo);
    SYM(snT_hi, d_snT_hi); SYM(snT_lo, d_snT_lo);
    SYM(fsT_hi, d_fsT_hi); SYM(fsT_lo, d_fsT_lo);
    SYM(thw_hi, d_thw_hi); SYM(thw_lo, d_thw_lo);
    SYM(phw_hi, d_phw_hi); SYM(phw_lo, d_phw_lo);
    SYM(gw_hi,  d_gw_hi);  SYM(gw_lo,  d_gw_lo);
    SYM(Ww_hi,  d_Ww_hi);  SYM(Ww_lo,  d_Ww_lo);
    SYM(thT_hi, d_thT_hi); SYM(thT_lo, d_thT_lo);
    SYM(phT_hi, d_phT_hi); SYM(phT_lo, d_phT_lo);
    SYM(gT_hi,  d_gT_hi);  SYM(gT_lo,  d_gT_lo);
    SYM(Pp,     d_P);
    SYM(y_hi,   d_y_hi);   SYM(y_lo,   d_y_lo);
    SYM(Gp,     d_G);

    // 1) instance-norm stats
    stats_kernel<<<2 * BB * CC, 256>>>(content, style);
    // 2) normalize + transpose + split
    norm_split_T<<<dim3(HWH / 32, CC / 32, 3 * BB), dim3(32, 8)>>>(content, style, fusion);
    // 3) weight splits
    weight_split<<<(ICI * CC) / 256, 256>>>((const float*)d_in[3], (const float*)d_in[5],
                                            (const float*)d_in[7], (const float*)d_in[9]);

    // 4) theta_xT = xnT @ theta_w^T + theta_b : M=4096, N=256, K=512 (NST=3)
    LAUNCH_GEMM(0, 1, 1, 1, 2, 4, 2, 128, 64, 3,
                xnT_hi, xnT_lo, thw_hi, thw_lo, theta_b, thT_hi, thT_lo,
                HWH, ICI, CC, (long long)HWH * CC, 0LL, (long long)HWH * ICI);

    // 5) phi_sT = snT @ phi_w^T + phi_b (NST=3)
    LAUNCH_GEMM(0, 1, 1, 1, 2, 4, 2, 128, 64, 3,
                snT_hi, snT_lo, phw_hi, phw_lo, phi_b, phT_hi, phT_lo,
                HWH, ICI, CC, (long long)HWH * CC, 0LL, (long long)HWH * ICI);

    // 6) g_sT = g_w @ fsT^T + g_b : M=256, N=4096, K=512 -> split fp16 (NST=3)
    LAUNCH_GEMM(0, 1, 1, 2, 1, 4, 2, 128, 64, 3,
                gw_hi, gw_lo, fsT_hi, fsT_lo, g_b, gT_hi, gT_lo,
                ICI, HWH, CC, 0LL, (long long)HWH * CC, (long long)ICI * HWH);

    // 7) G = theta_xT @ phi_sT^T : M=N=4096, K=256 -> fp32 (NST=2, 2 CTA/SM)
    LAUNCH_GEMM(0, 1, 1, 0, 0, 2, 4, 128, 128, 2,
                thT_hi, thT_lo, phT_hi, phT_lo, (const float*)nullptr, Gp, (void*)nullptr,
                HWH, HWH, ICI, (long long)HWH * ICI, (long long)HWH * ICI, (long long)HWH * HWH);

    // 8) gather + softmax -> P (fp16)
    attn_softmax_kernel<<<dim3(HWH, BB), 256>>>(scale);

    // 9) y = P @ g_s : M=4096, N=256, K=4096, fp16 A x split fp16 B (NST=3)
    LAUNCH_GEMM(1, 0, 1, 1, 0, 2, 4, 128, 128, 3,
                Pp, Pp, gT_hi, gT_lo, (const float*)nullptr, y_hi, y_lo,
                HWH, ICI, HWH, (long long)HWH * HWH, (long long)ICI * HWH, (long long)HWH * ICI);

    // 10) out = W_w @ y^T + W_b : M=512, N=4096, K=256 -> fp32 (NST=2)
    LAUNCH_GEMM(0, 1, 1, 0, 1, 2, 4, 128, 128, 2,
                Ww_hi, Ww_lo, y_hi, y_lo, W_b, out, (void*)nullptr,
                CC, HWH, ICI, 0LL, (long long)HWH * ICI, (long long)CC * HWH);
}